// round 7
// baseline (speedup 1.0000x reference)
#include <cuda_runtime.h>
#include <cstdint>

// Problem dimensions (fixed by the dataset)
#define BB 16
#define NN 32768
#define CC 128
#define SS 1024

// FPS kernel tiling
#define GG 8                 // CTAs per batch == cluster size (portable max)
#define TT 256               // threads per CTA
#define CHUNK (NN / GG)      // 4096 points per CTA
#define KK (CHUNK / TT)      // 16 points per thread (registers)
#define PP (KK / 2)          // 8 packed f32x2 pairs per thread

// Scratch (allocation-free rule: __device__ globals)
__device__ float g_px[BB * NN];
__device__ float g_py[BB * NN];
__device__ float g_pz[BB * NN];
__device__ int   g_idx[BB * SS];

// ---------------------------------------------------------------------------
// Packed f32x2 helpers (sm_103a): each op = two independent .rn float ops,
// bit-identical to the scalar sequence.
// ---------------------------------------------------------------------------
__device__ __forceinline__ uint64_t pk2(float lo, float hi) {
    uint64_t r; asm("mov.b64 %0, {%1, %2};" : "=l"(r) : "f"(lo), "f"(hi)); return r;
}
__device__ __forceinline__ void up2(float& lo, float& hi, uint64_t v) {
    asm("mov.b64 {%0, %1}, %2;" : "=f"(lo), "=f"(hi) : "l"(v));
}
__device__ __forceinline__ uint64_t add2(uint64_t a, uint64_t b) {
    uint64_t r; asm("add.rn.f32x2 %0, %1, %2;" : "=l"(r) : "l"(a), "l"(b)); return r;
}
__device__ __forceinline__ uint64_t mul2(uint64_t a, uint64_t b) {
    uint64_t r; asm("mul.rn.f32x2 %0, %1, %2;" : "=l"(r) : "l"(a), "l"(b)); return r;
}

// Key packing: distances are >= 0, so bits(v) is monotone; key = bits(v)<<32 |
// ~idx makes u64 max == "max v, ties -> lowest idx" (JAX first-max argmax).
__device__ __forceinline__ uint64_t pack_key(float v, int idx) {
    return ((uint64_t)__float_as_uint(v) << 32) |
           (uint64_t)(0xFFFFFFFFu - (uint32_t)idx);
}
__device__ __forceinline__ int key_idx(uint64_t k) {
    return (int)(0xFFFFFFFFu - (uint32_t)k);
}

// ---------------------------------------------------------------------------
// Prep: transpose p [B, N, 3] (AoS) -> SoA px/py/pz for coalesced loads.
// ---------------------------------------------------------------------------
__global__ void prep_kernel(const float* __restrict__ p) {
    int i = blockIdx.x * blockDim.x + threadIdx.x;
    if (i < BB * NN) {
        const float* s = p + 3 * (size_t)i;
        g_px[i] = __ldg(s + 0);
        g_py[i] = __ldg(s + 1);
        g_pz[i] = __ldg(s + 2);
    }
}

// ---------------------------------------------------------------------------
// Cluster helpers
// ---------------------------------------------------------------------------
__device__ __forceinline__ uint32_t mapa_u32(uint32_t addr, uint32_t rank) {
    uint32_t r;
    asm("mapa.shared::cluster.u32 %0, %1, %2;" : "=r"(r) : "r"(addr), "r"(rank));
    return r;
}
__device__ __forceinline__ void st_cluster_v4(uint32_t addr, float a, float b,
                                              float c, float d) {
    asm volatile("st.shared::cluster.v4.f32 [%0], {%1, %2, %3, %4};"
                 :: "r"(addr), "f"(a), "f"(b), "f"(c), "f"(d) : "memory");
}

// Cluster record: {key_lo, key_hi, x, y} in v4 slot, z at +16. 32 B stride
// per rank -> broadcast LDS reads are conflict-free.
struct __align__(32) Rec {
    float4 a;   // {key_lo, key_hi, x, y}
    float  z;
    float  pad[3];
};

// ---------------------------------------------------------------------------
// Main FPS kernel: one cluster of GG CTAs per batch; points in registers.
// Per step: f32x2 distance update + tournament argmax -> key-only warp
// butterfly -> CTA tree-reduce + DSMEM record push -> cluster barrier ->
// record tree-reduce -> next q. One STG per step (the winning index).
// ---------------------------------------------------------------------------
__global__ void __cluster_dims__(GG, 1, 1) __launch_bounds__(TT, 1)
fps_kernel() {
    const int b    = blockIdx.x / GG;
    const int r    = blockIdx.x % GG;
    const int t    = threadIdx.x;
    const int w    = t >> 5;

    __shared__ uint64_t wk_s[TT / 32];
    __shared__ float    wx_s[TT / 32], wy_s[TT / 32], wz_s[TT / 32];
    __shared__ Rec rec[2][GG];   // double-buffered DSMEM-written records

    // Load 16 points/thread, packed as 8 f32x2 pairs (points 2j and 2j+1).
    uint64_t PX[PP], PY[PP], PZ[PP];
    float MD[KK];
    const int base = b * NN + r * CHUNK;
#pragma unroll
    for (int j = 0; j < PP; j++) {
        int lo = base + (2 * j) * TT + t;
        int hi = base + (2 * j + 1) * TT + t;
        PX[j] = pk2(g_px[lo], g_px[hi]);
        PY[j] = pk2(g_py[lo], g_py[hi]);
        PZ[j] = pk2(g_pz[lo], g_pz[hi]);
    }
#pragma unroll
    for (int k = 0; k < KK; k++) MD[k] = 3.402823466e38f;  // FLT_MAX (ref init)

    const int idx0 = r * CHUNK + t;   // batch-local idx of point k: idx0 + k*TT

    float qx = g_px[b * NN], qy = g_py[b * NN], qz = g_pz[b * NN];
    if (r == 0 && t == 0) g_idx[b * SS] = 0;

    for (int i = 1; i < SS; i++) {
        // ---- Phase 1: packed distance update + tournament argmax.
        // x - q computed as x + (-q): IEEE-exact identity; packed ops are
        // two independent .rn ops == scalar reference order ((dx^2+dy^2)+dz^2).
        uint64_t nqx2 = pk2(-qx, -qx);
        uint64_t nqy2 = pk2(-qy, -qy);
        uint64_t nqz2 = pk2(-qz, -qz);

        float v8[PP]; int k8[PP];
#pragma unroll
        for (int j = 0; j < PP; j++) {
            uint64_t dx2 = add2(PX[j], nqx2);
            uint64_t dy2 = add2(PY[j], nqy2);
            uint64_t dz2 = add2(PZ[j], nqz2);
            uint64_t d2  = add2(add2(mul2(dx2, dx2), mul2(dy2, dy2)),
                                mul2(dz2, dz2));
            float dlo, dhi; up2(dlo, dhi, d2);
            float m0 = fminf(MD[2 * j],     dlo); MD[2 * j]     = m0;
            float m1 = fminf(MD[2 * j + 1], dhi); MD[2 * j + 1] = m1;
            // Leaf: right (higher idx) wins iff strictly greater -> first-max.
            bool g = m1 > m0;
            v8[j] = g ? m1 : m0;
            k8[j] = g ? (2 * j + 1) : (2 * j);
        }
        // Tournament levels (right child = strictly larger indices; strict '>'
        // preserves first-max at every node).
        float v4[4]; int k4[4];
#pragma unroll
        for (int j = 0; j < 4; j++) {
            bool g = v8[2 * j + 1] > v8[2 * j];
            v4[j] = g ? v8[2 * j + 1] : v8[2 * j];
            k4[j] = g ? k8[2 * j + 1] : k8[2 * j];
        }
        float v2a[2]; int k2a[2];
#pragma unroll
        for (int j = 0; j < 2; j++) {
            bool g = v4[2 * j + 1] > v4[2 * j];
            v2a[j] = g ? v4[2 * j + 1] : v4[2 * j];
            k2a[j] = g ? k4[2 * j + 1] : k4[2 * j];
        }
        bool gf = v2a[1] > v2a[0];
        float bv = gf ? v2a[1] : v2a[0];
        int   bk = gf ? k2a[1] : k2a[0];

        // Recover winner coords (unrolled select; no dynamic reg indexing).
        uint64_t pxw = PX[0], pyw = PY[0], pzw = PZ[0];
#pragma unroll
        for (int j = 1; j < PP; j++) {
            if ((bk >> 1) == j) { pxw = PX[j]; pyw = PY[j]; pzw = PZ[j]; }
        }
        float x0, x1, y0, y1, z0, z1;
        up2(x0, x1, pxw); up2(y0, y1, pyw); up2(z0, z1, pzw);
        bool odd = (bk & 1);
        float bx = odd ? x1 : x0, by = odd ? y1 : y0, bz = odd ? z1 : z0;

        uint64_t mykey = pack_key(bv, idx0 + bk * TT);
        uint64_t key   = mykey;

        // ---- Warp butterfly reduce on the key ONLY (2 SHFLs/level).
#pragma unroll
        for (int s = 16; s > 0; s >>= 1) {
            uint64_t ok = __shfl_xor_sync(0xffffffffu, key, s);
            if (ok > key) key = ok;
        }
        // Keys are unique (embed idx) -> exactly one lane matches the max;
        // that lane writes the warp record (key + its own coords).
        if (key == mykey) {
            wk_s[w] = key; wx_s[w] = bx; wy_s[w] = by; wz_s[w] = bz;
        }
        __syncthreads();

        const int par = i & 1;
        // ---- Threads 0..GG-1: tree-reduce the 8 warp records (broadcast
        //      LDS, conflict-free) and push the CTA record to peer CTA `t`.
        if (t < GG) {
            uint64_t kk8[TT / 32]; float xs[TT / 32], ys[TT / 32], zs[TT / 32];
#pragma unroll
            for (int j = 0; j < TT / 32; j++) {
                kk8[j] = wk_s[j]; xs[j] = wx_s[j]; ys[j] = wy_s[j]; zs[j] = wz_s[j];
            }
#pragma unroll
            for (int st = 1; st < TT / 32; st <<= 1) {
#pragma unroll
                for (int j = 0; j < TT / 32; j += 2 * st) {
                    if (kk8[j + st] > kk8[j]) {
                        kk8[j] = kk8[j + st]; xs[j] = xs[j + st];
                        ys[j] = ys[j + st];   zs[j] = zs[j + st];
                    }
                }
            }
            uint32_t local0 = (uint32_t)__cvta_generic_to_shared(&rec[par][r]);
            uint32_t rem    = mapa_u32(local0, (uint32_t)t);
            st_cluster_v4(rem, __uint_as_float((uint32_t)kk8[0]),
                               __uint_as_float((uint32_t)(kk8[0] >> 32)),
                               xs[0], ys[0]);
            asm volatile("st.shared::cluster.f32 [%0], %1;"
                         :: "r"(rem + 16), "f"(zs[0]) : "memory");
        }

        // One cluster barrier per step (orders DSMEM stores; CTA-wide too).
        asm volatile("barrier.cluster.arrive.aligned;" ::: "memory");
        asm volatile("barrier.cluster.wait.aligned;"   ::: "memory");

        // ---- Phase 2: tree-reduce the GG records (depth 3) -> next q.
        uint64_t ck[GG]; float cx[GG], cy[GG], cz[GG];
#pragma unroll
        for (int j = 0; j < GG; j++) {
            float4 a = rec[par][j].a;
            ck[j] = ((uint64_t)__float_as_uint(a.y) << 32) |
                    (uint64_t)__float_as_uint(a.x);
            cx[j] = a.z; cy[j] = a.w; cz[j] = rec[par][j].z;
        }
#pragma unroll
        for (int st = 1; st < GG; st <<= 1) {
#pragma unroll
            for (int j = 0; j < GG; j += 2 * st) {
                if (ck[j + st] > ck[j]) {
                    ck[j] = ck[j + st]; cx[j] = cx[j + st];
                    cy[j] = cy[j + st]; cz[j] = cz[j + st];
                }
            }
        }
        qx = cx[0]; qy = cy[0]; qz = cz[0];
        if (r == 0 && t == 0) g_idx[b * SS + i] = key_idx(ck[0]);
    }
}

// ---------------------------------------------------------------------------
// Fused gather: p_out [B, S, 3] then x_out [B, C, S] in d_out.
// ---------------------------------------------------------------------------
__global__ void gather_kernel(const float* __restrict__ p,
                              const float* __restrict__ x,
                              float* __restrict__ out) {
    int tid = blockIdx.x * blockDim.x + threadIdx.x;
    if (tid < BB * SS) {
        int b   = tid / SS;
        int idx = g_idx[tid];
        const float* src = p + ((size_t)b * NN + idx) * 3;
        float* dst = out + (size_t)tid * 3;
        float v0 = __ldg(src + 0);
        float v1 = __ldg(src + 1);
        float v2 = __ldg(src + 2);
        dst[0] = v0; dst[1] = v1; dst[2] = v2;
    } else if (tid < BB * SS + BB * CC * SS) {
        int e  = tid - BB * SS;
        int s  = e % SS;
        int bc = e / SS;
        int b  = bc / CC;
        int idx = g_idx[b * SS + s];
        out[BB * SS * 3 + e] = __ldg(x + (size_t)bc * NN + idx);
    }
}

// ---------------------------------------------------------------------------
// Launch: prep -> FPS -> fused gather. Graph-capturable, allocation-free.
// ---------------------------------------------------------------------------
extern "C" void kernel_launch(void* const* d_in, const int* in_sizes, int n_in,
                              void* d_out, int out_size) {
    const float* p = (const float*)d_in[0];   // [B, N, 3]
    const float* x = (const float*)d_in[1];   // [B, C, N]
    float* out = (float*)d_out;

    prep_kernel<<<(BB * NN + 255) / 256, 256>>>(p);
    fps_kernel<<<BB * GG, TT>>>();
    const int gtotal = BB * SS + BB * CC * SS;
    gather_kernel<<<(gtotal + 255) / 256, 256>>>(p, x, out);
}

// round 12
// speedup vs baseline: 1.3015x; 1.3015x over previous
#include <cuda_runtime.h>
#include <cstdint>

// Problem dimensions (fixed by the dataset)
#define BB 16
#define NN 32768
#define CC 128
#define SS 1024

// FPS kernel tiling
#define GG 8                 // CTAs per batch == cluster size (portable max)
#define TT 256               // threads per CTA
#define CHUNK (NN / GG)      // 4096 points per CTA
#define KK (CHUNK / TT)      // 16 points per thread (registers)

// Scratch (allocation-free rule: __device__ globals)
__device__ float g_px[BB * NN];
__device__ float g_py[BB * NN];
__device__ float g_pz[BB * NN];
__device__ int   g_idx[BB * SS];

// Key packing: distances are >= 0, so bits(v) is monotone; key = bits(v)<<32 |
// ~idx makes u64 max == "max v, ties -> lowest idx" (JAX first-max argmax).
__device__ __forceinline__ uint64_t pack_key(float v, int idx) {
    return ((uint64_t)__float_as_uint(v) << 32) |
           (uint64_t)(0xFFFFFFFFu - (uint32_t)idx);
}
__device__ __forceinline__ int key_idx(uint64_t k) {
    return (int)(0xFFFFFFFFu - (uint32_t)k);
}

// ---------------------------------------------------------------------------
// Prep: transpose p [B, N, 3] (AoS) -> SoA px/py/pz for coalesced loads.
// ---------------------------------------------------------------------------
__global__ void prep_kernel(const float* __restrict__ p) {
    int i = blockIdx.x * blockDim.x + threadIdx.x;
    if (i < BB * NN) {
        const float* s = p + 3 * (size_t)i;
        g_px[i] = __ldg(s + 0);
        g_py[i] = __ldg(s + 1);
        g_pz[i] = __ldg(s + 2);
    }
}

// ---------------------------------------------------------------------------
// Cluster helpers
// ---------------------------------------------------------------------------
__device__ __forceinline__ uint32_t mapa_u32(uint32_t addr, uint32_t rank) {
    uint32_t r;
    asm("mapa.shared::cluster.u32 %0, %1, %2;" : "=r"(r) : "r"(addr), "r"(rank));
    return r;
}
__device__ __forceinline__ void st_cluster_v4(uint32_t addr, float a, float b,
                                              float c, float d) {
    asm volatile("st.shared::cluster.v4.f32 [%0], {%1, %2, %3, %4};"
                 :: "r"(addr), "f"(a), "f"(b), "f"(c), "f"(d) : "memory");
}

// Cluster record: {key_lo, key_hi, x, y} in v4 slot, z at +16. 32 B stride
// per rank -> broadcast LDS reads are conflict-free.
struct __align__(32) Rec {
    float4 a;   // {key_lo, key_hi, x, y}
    float  z;
    float  pad[3];
};

// ---------------------------------------------------------------------------
// Main FPS kernel: one cluster of GG CTAs per batch; points in registers.
// SCALAR distance math (R5-proven, ~90 regs, no spills). Changes vs R5:
//   - phase-1 argmax via depth-4 tournament (breaks the 16-deep select chain)
//   - warp reduce shuffles the packed key ONLY (10 SHFLs vs 25)
// ---------------------------------------------------------------------------
__global__ void __cluster_dims__(GG, 1, 1) __launch_bounds__(TT, 1)
fps_kernel() {
    const int b    = blockIdx.x / GG;
    const int r    = blockIdx.x % GG;
    const int t    = threadIdx.x;
    const int w    = t >> 5;

    __shared__ uint64_t wk_s[TT / 32];
    __shared__ float    wx_s[TT / 32], wy_s[TT / 32], wz_s[TT / 32];
    __shared__ Rec rec[2][GG];   // double-buffered DSMEM-written records

    // Load this thread's 16 points into registers (coalesced from SoA).
    float X[KK], Y[KK], Z[KK], MD[KK];
    const int base = b * NN + r * CHUNK;
#pragma unroll
    for (int k = 0; k < KK; k++) {
        int li = k * TT + t;
        X[k]  = g_px[base + li];
        Y[k]  = g_py[base + li];
        Z[k]  = g_pz[base + li];
        MD[k] = 3.402823466e38f;   // finfo(float32).max, matches reference init
    }

    const int idx0 = r * CHUNK + t;   // batch-local idx of point k: idx0 + k*TT

    float qx = g_px[b * NN], qy = g_py[b * NN], qz = g_pz[b * NN];
    if (r == 0 && t == 0) g_idx[b * SS] = 0;

    for (int i = 1; i < SS; i++) {
        // ---- Phase 1: scalar distance update (reference op order, no FMA
        //      contraction: d = ((dx*dx + dy*dy) + dz*dz)), then tournament
        //      argmax over MD[0..15].
#pragma unroll
        for (int k = 0; k < KK; k++) {
            float dx = __fsub_rn(X[k], qx);
            float dy = __fsub_rn(Y[k], qy);
            float dz = __fsub_rn(Z[k], qz);
            float d  = __fadd_rn(__fadd_rn(__fmul_rn(dx, dx), __fmul_rn(dy, dy)),
                                 __fmul_rn(dz, dz));
            MD[k] = fminf(MD[k], d);
        }
        // Tournament: right child covers strictly larger indices and wins only
        // on strict '>' -> first-max (lowest index on ties) at every node.
        float v8[8]; int k8[8];
#pragma unroll
        for (int j = 0; j < 8; j++) {
            bool g = MD[2 * j + 1] > MD[2 * j];
            v8[j] = g ? MD[2 * j + 1] : MD[2 * j];
            k8[j] = g ? (2 * j + 1) : (2 * j);
        }
        float v4[4]; int k4[4];
#pragma unroll
        for (int j = 0; j < 4; j++) {
            bool g = v8[2 * j + 1] > v8[2 * j];
            v4[j] = g ? v8[2 * j + 1] : v8[2 * j];
            k4[j] = g ? k8[2 * j + 1] : k8[2 * j];
        }
        float v2a[2]; int k2a[2];
#pragma unroll
        for (int j = 0; j < 2; j++) {
            bool g = v4[2 * j + 1] > v4[2 * j];
            v2a[j] = g ? v4[2 * j + 1] : v4[2 * j];
            k2a[j] = g ? k4[2 * j + 1] : k4[2 * j];
        }
        bool gf = v2a[1] > v2a[0];
        float bv = gf ? v2a[1] : v2a[0];
        int   bk = gf ? k2a[1] : k2a[0];

        // Recover winner coords (unrolled select; no dynamic reg indexing).
        float bx = X[0], by = Y[0], bz = Z[0];
#pragma unroll
        for (int k = 1; k < KK; k++) {
            if (bk == k) { bx = X[k]; by = Y[k]; bz = Z[k]; }
        }

        uint64_t mykey = pack_key(bv, idx0 + bk * TT);
        uint64_t key   = mykey;

        // ---- Warp butterfly reduce on the key ONLY (2 SHFLs/level).
#pragma unroll
        for (int s = 16; s > 0; s >>= 1) {
            uint64_t ok = __shfl_xor_sync(0xffffffffu, key, s);
            if (ok > key) key = ok;
        }
        // Keys are unique (embed idx) -> exactly one lane matches the max;
        // that lane writes the warp record (key + its own coords).
        if (key == mykey) {
            wk_s[w] = key; wx_s[w] = bx; wy_s[w] = by; wz_s[w] = bz;
        }
        __syncthreads();

        const int par = i & 1;
        // ---- Threads 0..GG-1: tree-reduce the 8 warp records (broadcast
        //      LDS, conflict-free) and push the CTA record to peer CTA `t`.
        if (t < GG) {
            uint64_t kk8[TT / 32]; float xs[TT / 32], ys[TT / 32], zs[TT / 32];
#pragma unroll
            for (int j = 0; j < TT / 32; j++) {
                kk8[j] = wk_s[j]; xs[j] = wx_s[j]; ys[j] = wy_s[j]; zs[j] = wz_s[j];
            }
#pragma unroll
            for (int st = 1; st < TT / 32; st <<= 1) {
#pragma unroll
                for (int j = 0; j < TT / 32; j += 2 * st) {
                    if (kk8[j + st] > kk8[j]) {
                        kk8[j] = kk8[j + st]; xs[j] = xs[j + st];
                        ys[j] = ys[j + st];   zs[j] = zs[j + st];
                    }
                }
            }
            uint32_t local0 = (uint32_t)__cvta_generic_to_shared(&rec[par][r]);
            uint32_t rem    = mapa_u32(local0, (uint32_t)t);
            st_cluster_v4(rem, __uint_as_float((uint32_t)kk8[0]),
                               __uint_as_float((uint32_t)(kk8[0] >> 32)),
                               xs[0], ys[0]);
            asm volatile("st.shared::cluster.f32 [%0], %1;"
                         :: "r"(rem + 16), "f"(zs[0]) : "memory");
        }

        // One cluster barrier per step (orders DSMEM stores; CTA-wide too).
        asm volatile("barrier.cluster.arrive.aligned;" ::: "memory");
        asm volatile("barrier.cluster.wait.aligned;"   ::: "memory");

        // ---- Phase 2: tree-reduce the GG records (depth 3) -> next q.
        uint64_t ck[GG]; float cx[GG], cy[GG], cz[GG];
#pragma unroll
        for (int j = 0; j < GG; j++) {
            float4 a = rec[par][j].a;
            ck[j] = ((uint64_t)__float_as_uint(a.y) << 32) |
                    (uint64_t)__float_as_uint(a.x);
            cx[j] = a.z; cy[j] = a.w; cz[j] = rec[par][j].z;
        }
#pragma unroll
        for (int st = 1; st < GG; st <<= 1) {
#pragma unroll
            for (int j = 0; j < GG; j += 2 * st) {
                if (ck[j + st] > ck[j]) {
                    ck[j] = ck[j + st]; cx[j] = cx[j + st];
                    cy[j] = cy[j + st]; cz[j] = cz[j + st];
                }
            }
        }
        qx = cx[0]; qy = cy[0]; qz = cz[0];
        if (r == 0 && t == 0) g_idx[b * SS + i] = key_idx(ck[0]);
    }
}

// ---------------------------------------------------------------------------
// Fused gather: p_out [B, S, 3] then x_out [B, C, S] in d_out.
// ---------------------------------------------------------------------------
__global__ void gather_kernel(const float* __restrict__ p,
                              const float* __restrict__ x,
                              float* __restrict__ out) {
    int tid = blockIdx.x * blockDim.x + threadIdx.x;
    if (tid < BB * SS) {
        int b   = tid / SS;
        int idx = g_idx[tid];
        const float* src = p + ((size_t)b * NN + idx) * 3;
        float* dst = out + (size_t)tid * 3;
        float v0 = __ldg(src + 0);
        float v1 = __ldg(src + 1);
        float v2 = __ldg(src + 2);
        dst[0] = v0; dst[1] = v1; dst[2] = v2;
    } else if (tid < BB * SS + BB * CC * SS) {
        int e  = tid - BB * SS;
        int s  = e % SS;
        int bc = e / SS;
        int b  = bc / CC;
        int idx = g_idx[b * SS + s];
        out[BB * SS * 3 + e] = __ldg(x + (size_t)bc * NN + idx);
    }
}

// ---------------------------------------------------------------------------
// Launch: prep -> FPS -> fused gather. Graph-capturable, allocation-free.
// ---------------------------------------------------------------------------
extern "C" void kernel_launch(void* const* d_in, const int* in_sizes, int n_in,
                              void* d_out, int out_size) {
    const float* p = (const float*)d_in[0];   // [B, N, 3]
    const float* x = (const float*)d_in[1];   // [B, C, N]
    float* out = (float*)d_out;

    prep_kernel<<<(BB * NN + 255) / 256, 256>>>(p);
    fps_kernel<<<BB * GG, TT>>>();
    const int gtotal = BB * SS + BB * CC * SS;
    gather_kernel<<<(gtotal + 255) / 256, 256>>>(p, x, out);
}

// round 15
// speedup vs baseline: 1.3903x; 1.0682x over previous
#include <cuda_runtime.h>
#include <cstdint>

// Problem dimensions (fixed by the dataset)
#define BB 16
#define NN 32768
#define CC 128
#define SS 1024

// FPS kernel tiling
#define GG 8                 // CTAs per batch == cluster size (portable max)
#define TT 256               // threads per CTA
#define CHUNK (NN / GG)      // 4096 points per CTA
#define KK (CHUNK / TT)      // 16 points per thread (live in registers)

// Scratch (allocation-free rule: __device__ globals)
__device__ float g_px[BB * NN];
__device__ float g_py[BB * NN];
__device__ float g_pz[BB * NN];
__device__ int   g_idx[BB * SS];

// ---------------------------------------------------------------------------
// Prep: transpose p [B, N, 3] (AoS) -> SoA px/py/pz for coalesced loads.
// ---------------------------------------------------------------------------
__global__ void prep_kernel(const float* __restrict__ p) {
    int i = blockIdx.x * blockDim.x + threadIdx.x;
    if (i < BB * NN) {
        const float* s = p + 3 * (size_t)i;
        g_px[i] = __ldg(s + 0);
        g_py[i] = __ldg(s + 1);
        g_pz[i] = __ldg(s + 2);
    }
}

// ---------------------------------------------------------------------------
// Cluster helpers
// ---------------------------------------------------------------------------
__device__ __forceinline__ uint32_t mapa_u32(uint32_t addr, uint32_t rank) {
    uint32_t r;
    asm("mapa.shared::cluster.u32 %0, %1, %2;" : "=r"(r) : "r"(addr), "r"(rank));
    return r;
}
__device__ __forceinline__ void st_cluster_v4(uint32_t addr, float a, float b,
                                              float c, float d) {
    asm volatile("st.shared::cluster.v4.f32 [%0], {%1, %2, %3, %4};"
                 :: "r"(addr), "f"(a), "f"(b), "f"(c), "f"(d) : "memory");
}
// Release-cluster arrive on a PEER CTA's mbarrier (orders prior cluster stores).
__device__ __forceinline__ void mbar_arrive_peer(uint32_t local_mbar, uint32_t rank) {
    uint32_t rem = mapa_u32(local_mbar, rank);
    asm volatile("mbarrier.arrive.release.cluster.shared::cluster.b64 _, [%0];"
                 :: "r"(rem) : "memory");
}
// Acquire-cluster parity wait on the LOCAL mbarrier.
__device__ __forceinline__ void mbar_wait_parity(uint32_t mbar, uint32_t parity) {
    asm volatile(
        "{\n\t"
        ".reg .pred P1;\n\t"
        "WAIT_LOOP_%=:\n\t"
        "mbarrier.try_wait.parity.acquire.cluster.shared::cta.b64 P1, [%0], %1, 0x989680;\n\t"
        "@P1 bra.uni WAIT_DONE_%=;\n\t"
        "bra.uni WAIT_LOOP_%=;\n\t"
        "WAIT_DONE_%=:\n\t"
        "}"
        :: "r"(mbar), "r"(parity) : "memory");
}

// Cluster record: {v, idx, x, y} in v4 slot, z at +16. 32 B stride per rank.
struct __align__(32) Rec {
    float4 a;   // {v, idx_bits, x, y}
    float  z;
    float  pad[3];
};

// ---------------------------------------------------------------------------
// Main FPS kernel — R5 compute core verbatim (1343us-proven). ONLY the
// per-step cluster barrier is replaced by a ring of TWO mbarriers:
//   step i: push records to peers (st.shared::cluster) -> release-arrive on
//   each peer's mbar[i&1] -> all threads acquire-wait parity on local
//   mbar[i&1]. The 2-deep ring makes over-arrival structurally impossible
//   (a step-i+2 arrival on mbar[i&1] requires step-i+1's wait to have
//   completed on every rank, which requires phase i to have drained).
// ---------------------------------------------------------------------------
__global__ void __cluster_dims__(GG, 1, 1) __launch_bounds__(TT, 1)
fps_kernel() {
    const int b    = blockIdx.x / GG;   // batch
    const int r    = blockIdx.x % GG;   // cluster rank (chunk)
    const int t    = threadIdx.x;
    const int w    = t >> 5;
    const int lane = t & 31;

    __shared__ float wv_s[TT / 32];
    __shared__ int   wi_s[TT / 32];
    __shared__ float wx_s[TT / 32], wy_s[TT / 32], wz_s[TT / 32];
    __shared__ Rec rec[2][GG];               // double-buffered DSMEM records
    __shared__ __align__(8) uint64_t mbar_store[2];

    const uint32_t mbar0 = (uint32_t)__cvta_generic_to_shared(&mbar_store[0]);
    const uint32_t mbar1 = (uint32_t)__cvta_generic_to_shared(&mbar_store[1]);

    // Init both mbarriers (8 arrivals per phase: one per rank's pusher thread).
    if (t == 0) {
        asm volatile("mbarrier.init.shared.b64 [%0], %1;"
                     :: "r"(mbar0), "r"(GG) : "memory");
        asm volatile("mbarrier.init.shared.b64 [%0], %1;"
                     :: "r"(mbar1), "r"(GG) : "memory");
    }
    __syncthreads();
    // All mbarriers must be visible cluster-wide before any remote arrive.
    asm volatile("barrier.cluster.arrive.aligned;" ::: "memory");
    asm volatile("barrier.cluster.wait.aligned;"   ::: "memory");

    // Load this thread's 16 points into registers (coalesced from SoA).
    float X[KK], Y[KK], Z[KK], MD[KK];
    const int base = b * NN + r * CHUNK;
#pragma unroll
    for (int k = 0; k < KK; k++) {
        int li = k * TT + t;
        X[k]  = g_px[base + li];
        Y[k]  = g_py[base + li];
        Z[k]  = g_pz[base + li];
        MD[k] = 3.402823466e38f;   // finfo(float32).max, matches reference init
    }

    const int idx0 = r * CHUNK + t;   // batch-local idx of point k: idx0 + k*TT

    float qx = g_px[b * NN], qy = g_py[b * NN], qz = g_pz[b * NN];
    if (r == 0 && t == 0) g_idx[b * SS] = 0;

    int ph0 = 0, ph1 = 0;   // per-slot parity counters (identical on all threads)

    for (int i = 1; i < SS; i++) {
        // ---- Phase 1: distance update + thread-local argmax (R5 verbatim).
        float bv = -1.0f;
        int   gi = idx0;
        float bx = 0.f, by = 0.f, bz = 0.f;
#pragma unroll
        for (int k = 0; k < KK; k++) {
            // Reference op order, no FMA contraction: d = ((dx*dx + dy*dy) + dz*dz)
            float dx = __fsub_rn(X[k], qx);
            float dy = __fsub_rn(Y[k], qy);
            float dz = __fsub_rn(Z[k], qz);
            float d  = __fadd_rn(__fadd_rn(__fmul_rn(dx, dx), __fmul_rn(dy, dy)),
                                 __fmul_rn(dz, dz));
            float m  = fminf(MD[k], d);
            MD[k]    = m;
            // Strict '>' keeps the lowest index on ties (k ascending => idx ascending)
            if (m > bv) { bv = m; gi = idx0 + k * TT; bx = X[k]; by = Y[k]; bz = Z[k]; }
        }

        // ---- Warp argmax reduce carrying coords (R5 verbatim).
#pragma unroll
        for (int s = 16; s > 0; s >>= 1) {
            float ov = __shfl_down_sync(0xffffffffu, bv, s);
            int   oi = __shfl_down_sync(0xffffffffu, gi, s);
            float ox = __shfl_down_sync(0xffffffffu, bx, s);
            float oy = __shfl_down_sync(0xffffffffu, by, s);
            float oz = __shfl_down_sync(0xffffffffu, bz, s);
            if (ov > bv || (ov == bv && oi < gi)) {
                bv = ov; gi = oi; bx = ox; by = oy; bz = oz;
            }
        }
        if (lane == 0) {
            wv_s[w] = bv; wi_s[w] = gi; wx_s[w] = bx; wy_s[w] = by; wz_s[w] = bz;
        }
        __syncthreads();

        const int par = i & 1;
        const uint32_t mbar = par ? mbar1 : mbar0;
        // ---- Threads 0..GG-1: reduce the 8 warp records (R5 verbatim) and
        //      push the CTA record to peer CTA `t`, then release-arrive on
        //      peer t's mbar[par].
        if (t < GG) {
            float v = wv_s[0]; int idx = wi_s[0];
            float xx = wx_s[0], yy = wy_s[0], zz = wz_s[0];
#pragma unroll
            for (int j = 1; j < TT / 32; j++) {
                float v2 = wv_s[j]; int i2 = wi_s[j];
                if (v2 > v || (v2 == v && i2 < idx)) {
                    v = v2; idx = i2; xx = wx_s[j]; yy = wy_s[j]; zz = wz_s[j];
                }
            }
            uint32_t local0 = (uint32_t)__cvta_generic_to_shared(&rec[par][r]);
            uint32_t rem    = mapa_u32(local0, (uint32_t)t);
            st_cluster_v4(rem, v, __int_as_float(idx), xx, yy);
            asm volatile("st.shared::cluster.f32 [%0], %1;"
                         :: "r"(rem + 16), "f"(zz) : "memory");
            mbar_arrive_peer(mbar, (uint32_t)t);
        }

        // ---- All threads: acquire-wait the 8 arrivals of this slot's phase.
        if (par) { mbar_wait_parity(mbar, (uint32_t)ph1); ph1 ^= 1; }
        else     { mbar_wait_parity(mbar, (uint32_t)ph0); ph0 ^= 1; }

        // ---- Phase 2: reduce the GG records (R5 verbatim) -> next q.
        float4 a0 = rec[par][0].a;
        float wvv = a0.x;
        int   wii = __float_as_int(a0.y);
        qx = a0.z; qy = a0.w; qz = rec[par][0].z;
#pragma unroll
        for (int j = 1; j < GG; j++) {
            float4 a2 = rec[par][j].a;
            float v2 = a2.x; int i2 = __float_as_int(a2.y);
            if (v2 > wvv || (v2 == wvv && i2 < wii)) {
                wvv = v2; wii = i2; qx = a2.z; qy = a2.w; qz = rec[par][j].z;
            }
        }
        if (r == 0 && t == 0) g_idx[b * SS + i] = wii;
    }

    // No CTA may exit while peers' remote stores could still target its smem.
    asm volatile("barrier.cluster.arrive.aligned;" ::: "memory");
    asm volatile("barrier.cluster.wait.aligned;"   ::: "memory");
}

// ---------------------------------------------------------------------------
// Fused gather: p_out [B, S, 3] then x_out [B, C, S] in d_out.
// ---------------------------------------------------------------------------
__global__ void gather_kernel(const float* __restrict__ p,
                              const float* __restrict__ x,
                              float* __restrict__ out) {
    int tid = blockIdx.x * blockDim.x + threadIdx.x;
    if (tid < BB * SS) {
        int b   = tid / SS;
        int idx = g_idx[tid];
        const float* src = p + ((size_t)b * NN + idx) * 3;
        float* dst = out + (size_t)tid * 3;
        float v0 = __ldg(src + 0);
        float v1 = __ldg(src + 1);
        float v2 = __ldg(src + 2);
        dst[0] = v0; dst[1] = v1; dst[2] = v2;
    } else if (tid < BB * SS + BB * CC * SS) {
        int e  = tid - BB * SS;
        int s  = e % SS;
        int bc = e / SS;
        int b  = bc / CC;
        int idx = g_idx[b * SS + s];
        out[BB * SS * 3 + e] = __ldg(x + (size_t)bc * NN + idx);
    }
}

// ---------------------------------------------------------------------------
// Launch: prep -> FPS -> fused gather. Graph-capturable, allocation-free.
// ---------------------------------------------------------------------------
extern "C" void kernel_launch(void* const* d_in, const int* in_sizes, int n_in,
                              void* d_out, int out_size) {
    const float* p = (const float*)d_in[0];   // [B, N, 3]
    const float* x = (const float*)d_in[1];   // [B, C, N]
    float* out = (float*)d_out;

    prep_kernel<<<(BB * NN + 255) / 256, 256>>>(p);
    fps_kernel<<<BB * GG, TT>>>();
    const int gtotal = BB * SS + BB * CC * SS;
    gather_kernel<<<(gtotal + 255) / 256, 256>>>(p, x, out);
}

// round 17
// speedup vs baseline: 1.4556x; 1.0470x over previous
#include <cuda_runtime.h>
#include <cstdint>

// Problem dimensions (fixed by the dataset)
#define BB 16
#define NN 32768
#define CC 128
#define SS 1024

// FPS kernel tiling
#define GG 8                 // CTAs per batch == cluster size (portable max)
#define TT 256               // threads per CTA
#define CHUNK (NN / GG)      // 4096 points per CTA
#define KK (CHUNK / TT)      // 16 points per thread (live in registers)

// Scratch (allocation-free rule: __device__ globals)
__device__ float g_px[BB * NN];
__device__ float g_py[BB * NN];
__device__ float g_pz[BB * NN];
__device__ int   g_idx[BB * SS];

// Key packing: distances are >= 0, so bits(v) is monotone; key = bits(v)<<32 |
// ~idx makes u64 max == "max v, ties -> lowest idx" (JAX first-max argmax).
__device__ __forceinline__ uint64_t pack_key(float v, int idx) {
    return ((uint64_t)__float_as_uint(v) << 32) |
           (uint64_t)(0xFFFFFFFFu - (uint32_t)idx);
}
__device__ __forceinline__ int key_idx(uint64_t k) {
    return (int)(0xFFFFFFFFu - (uint32_t)k);
}

// ---------------------------------------------------------------------------
// Prep: transpose p [B, N, 3] (AoS) -> SoA px/py/pz for coalesced loads.
// ---------------------------------------------------------------------------
__global__ void prep_kernel(const float* __restrict__ p) {
    int i = blockIdx.x * blockDim.x + threadIdx.x;
    if (i < BB * NN) {
        const float* s = p + 3 * (size_t)i;
        g_px[i] = __ldg(s + 0);
        g_py[i] = __ldg(s + 1);
        g_pz[i] = __ldg(s + 2);
    }
}

// ---------------------------------------------------------------------------
// Cluster helpers
// ---------------------------------------------------------------------------
__device__ __forceinline__ uint32_t mapa_u32(uint32_t addr, uint32_t rank) {
    uint32_t r;
    asm("mapa.shared::cluster.u32 %0, %1, %2;" : "=r"(r) : "r"(addr), "r"(rank));
    return r;
}
__device__ __forceinline__ void st_cluster_v4(uint32_t addr, float a, float b,
                                              float c, float d) {
    asm volatile("st.shared::cluster.v4.f32 [%0], {%1, %2, %3, %4};"
                 :: "r"(addr), "f"(a), "f"(b), "f"(c), "f"(d) : "memory");
}

// Cluster record: {key_lo, key_hi, x, y} in v4 slot, z at +16. 32 B stride
// per rank -> broadcast LDS reads are conflict-free.
struct __align__(32) Rec {
    float4 a;   // {key_lo, key_hi, x, y}
    float  z;
    float  pad[3];
};

// ---------------------------------------------------------------------------
// Main FPS kernel — R5 (1343us-proven) with EXACTLY ONE change: the warp
// argmax reduce shuffles a packed 64-bit key (2 SHFLs/level, single u64
// compare) instead of 5 separate values; the unique winner lane writes the
// warp record from its own registers. Everything else (linear phase-1 select
// chain, linear CTA/phase-2 reduces, DSMEM push, per-step barrier.cluster)
// keeps the R5 shape.
// ---------------------------------------------------------------------------
__global__ void __cluster_dims__(GG, 1, 1) __launch_bounds__(TT, 1)
fps_kernel() {
    const int b    = blockIdx.x / GG;   // batch
    const int r    = blockIdx.x % GG;   // cluster rank (chunk)
    const int t    = threadIdx.x;
    const int w    = t >> 5;

    __shared__ uint64_t wk_s[TT / 32];
    __shared__ float    wx_s[TT / 32], wy_s[TT / 32], wz_s[TT / 32];
    __shared__ Rec rec[2][GG];   // double-buffered DSMEM-written records

    // Load this thread's 16 points into registers (coalesced from SoA).
    float X[KK], Y[KK], Z[KK], MD[KK];
    const int base = b * NN + r * CHUNK;
#pragma unroll
    for (int k = 0; k < KK; k++) {
        int li = k * TT + t;
        X[k]  = g_px[base + li];
        Y[k]  = g_py[base + li];
        Z[k]  = g_pz[base + li];
        MD[k] = 3.402823466e38f;   // finfo(float32).max, matches reference init
    }

    const int idx0 = r * CHUNK + t;   // batch-local idx of point k: idx0 + k*TT

    float qx = g_px[b * NN], qy = g_py[b * NN], qz = g_pz[b * NN];
    if (r == 0 && t == 0) g_idx[b * SS] = 0;

    for (int i = 1; i < SS; i++) {
        // ---- Phase 1: distance update + thread-local argmax (R5 verbatim:
        //      linear select chain tracking value, index, and coords).
        float bv = -1.0f;
        int   gi = idx0;
        float bx = 0.f, by = 0.f, bz = 0.f;
#pragma unroll
        for (int k = 0; k < KK; k++) {
            // Reference op order, no FMA contraction: d = ((dx*dx + dy*dy) + dz*dz)
            float dx = __fsub_rn(X[k], qx);
            float dy = __fsub_rn(Y[k], qy);
            float dz = __fsub_rn(Z[k], qz);
            float d  = __fadd_rn(__fadd_rn(__fmul_rn(dx, dx), __fmul_rn(dy, dy)),
                                 __fmul_rn(dz, dz));
            float m  = fminf(MD[k], d);
            MD[k]    = m;
            // Strict '>' keeps the lowest index on ties (k ascending => idx ascending)
            if (m > bv) { bv = m; gi = idx0 + k * TT; bx = X[k]; by = Y[k]; bz = Z[k]; }
        }

        uint64_t mykey = pack_key(bv, gi);
        uint64_t key   = mykey;

        // ---- THE one change vs R5: butterfly reduce on the packed key ONLY
        //      (2 SHFLs + 1 u64 select per level instead of 5 SHFLs + double
        //      compare). Unique keys -> exactly one winner lane per warp.
#pragma unroll
        for (int s = 16; s > 0; s >>= 1) {
            uint64_t ok = __shfl_xor_sync(0xffffffffu, key, s);
            if (ok > key) key = ok;
        }
        if (key == mykey) {
            wk_s[w] = key; wx_s[w] = bx; wy_s[w] = by; wz_s[w] = bz;
        }
        __syncthreads();

        const int par = i & 1;
        // ---- Threads 0..GG-1: linear reduce of the 8 warp records (R5 shape,
        //      u64 key compares) and push the CTA record to peer CTA `t`.
        if (t < GG) {
            uint64_t kk = wk_s[0];
            float xx = wx_s[0], yy = wy_s[0], zz = wz_s[0];
#pragma unroll
            for (int j = 1; j < TT / 32; j++) {
                uint64_t k2 = wk_s[j];
                if (k2 > kk) { kk = k2; xx = wx_s[j]; yy = wy_s[j]; zz = wz_s[j]; }
            }
            uint32_t local0 = (uint32_t)__cvta_generic_to_shared(&rec[par][r]);
            uint32_t rem    = mapa_u32(local0, (uint32_t)t);
            st_cluster_v4(rem, __uint_as_float((uint32_t)kk),
                               __uint_as_float((uint32_t)(kk >> 32)), xx, yy);
            asm volatile("st.shared::cluster.f32 [%0], %1;"
                         :: "r"(rem + 16), "f"(zz) : "memory");
        }

        // One cluster barrier per step (R5/R15-proven cheapest sync: orders
        // the DSMEM stores and doubles as the CTA-wide barrier).
        asm volatile("barrier.cluster.arrive.aligned;" ::: "memory");
        asm volatile("barrier.cluster.wait.aligned;"   ::: "memory");

        // ---- Phase 2: linear reduce of the GG records (R5 shape, u64 keys).
        float4   a0  = rec[par][0].a;
        uint64_t wkk = ((uint64_t)__float_as_uint(a0.y) << 32) |
                       (uint64_t)__float_as_uint(a0.x);
        qx = a0.z; qy = a0.w; qz = rec[par][0].z;
#pragma unroll
        for (int j = 1; j < GG; j++) {
            float4   a2 = rec[par][j].a;
            uint64_t k2 = ((uint64_t)__float_as_uint(a2.y) << 32) |
                          (uint64_t)__float_as_uint(a2.x);
            if (k2 > wkk) { wkk = k2; qx = a2.z; qy = a2.w; qz = rec[par][j].z; }
        }
        if (r == 0 && t == 0) g_idx[b * SS + i] = key_idx(wkk);
    }
}

// ---------------------------------------------------------------------------
// Fused gather: p_out [B, S, 3] then x_out [B, C, S] in d_out.
// ---------------------------------------------------------------------------
__global__ void gather_kernel(const float* __restrict__ p,
                              const float* __restrict__ x,
                              float* __restrict__ out) {
    int tid = blockIdx.x * blockDim.x + threadIdx.x;
    if (tid < BB * SS) {
        int b   = tid / SS;
        int idx = g_idx[tid];
        const float* src = p + ((size_t)b * NN + idx) * 3;
        float* dst = out + (size_t)tid * 3;
        float v0 = __ldg(src + 0);
        float v1 = __ldg(src + 1);
        float v2 = __ldg(src + 2);
        dst[0] = v0; dst[1] = v1; dst[2] = v2;
    } else if (tid < BB * SS + BB * CC * SS) {
        int e  = tid - BB * SS;
        int s  = e % SS;
        int bc = e / SS;
        int b  = bc / CC;
        int idx = g_idx[b * SS + s];
        out[BB * SS * 3 + e] = __ldg(x + (size_t)bc * NN + idx);
    }
}

// ---------------------------------------------------------------------------
// Launch: prep -> FPS -> fused gather. Graph-capturable, allocation-free.
// ---------------------------------------------------------------------------
extern "C" void kernel_launch(void* const* d_in, const int* in_sizes, int n_in,
                              void* d_out, int out_size) {
    const float* p = (const float*)d_in[0];   // [B, N, 3]
    const float* x = (const float*)d_in[1];   // [B, C, N]
    float* out = (float*)d_out;

    prep_kernel<<<(BB * NN + 255) / 256, 256>>>(p);
    fps_kernel<<<BB * GG, TT>>>();
    const int gtotal = BB * SS + BB * CC * SS;
    gather_kernel<<<(gtotal + 255) / 256, 256>>>(p, x, out);
}